// round 2
// baseline (speedup 1.0000x reference)
#include <cuda_runtime.h>

// Problem constants
#define NBL 32   // B*L
#define NC  32   // channels (in == out)
#define NH  128
#define NW  256
#define NJ  32   // kept W-modes
#define NP  64   // kept H-rows: {0..31, 96..127}
#define NJC 64   // 2*NJ interleaved complex floats

// ---------------- scratch (__device__ globals; no allocations) ----------------
__device__ __align__(16) float g_T  [(size_t)NBL*NC*NH*NJC];   // fwd W-DFT of x   (33.5MB)
__device__ __align__(16) float g_Tk [(size_t)NC*NH*NJC];       // fwd W-DFT of k   (1MB)
__device__ __align__(16) float g_Z  [(size_t)NBL*NC*NP*NJ*2];  // x_f modes        (16.8MB)
__device__ __align__(16) float g_Kf [(size_t)NC*NP*NJ*2];      // k_f modes        (0.5MB)
__device__ __align__(16) float g_G  [(size_t)NBL*NC*NP*NJ*2];  // mixed modes      (16.8MB)
__device__ __align__(16) float g_tmp[(size_t)NBL*NC*NH*NJC];   // after inverse H  (33.5MB)
__device__ __align__(16) float g_DW [NW*NJC];                  // fwd W-DFT matrix [w][jc]
__device__ __align__(16) float g_CH [NH*NP];                   // fwd H twiddle cos [h][p]
__device__ __align__(16) float g_SH [NH*NP];                   // fwd H twiddle sin [h][p]
__device__ __align__(16) float g_CI [NP*NH];                   // inv H cos/H [p][h]
__device__ __align__(16) float g_SI [NP*NH];                   // inv H sin/H [p][h]
__device__ __align__(16) float g_DI [NJC*NW];                  // inv W c2r matrix [jc][w]
__device__ __align__(16) float g_Wmix[(size_t)NP*NJ*NC*NC*2];  // weights [p][j][c][o][2] (16.8MB)

__device__ __forceinline__ int row_of_p(int p) { return (p < 32) ? p : (64 + p); }

// ---------------- twiddle init ----------------
__global__ void init_twiddles() {
    int idx = blockIdx.x * blockDim.x + threadIdx.x;  // need >= 16384
    // g_DW[w][jc]: T = sum_w x * exp(-2*pi*i*j*w/W)  => Tr uses cos, Ti uses -sin
    if (idx < NW * NJC) {
        int w = idx / NJC, jc = idx % NJC, j = jc >> 1;
        int t = (j * w) % NW;
        float s, c; sincospif(2.0f * (float)t / (float)NW, &s, &c);
        g_DW[idx] = (jc & 1) ? -s : c;
    }
    // g_CH/g_SH [h][p] and g_CI/g_SI [p][h]
    if (idx < NH * NP) {
        {
            int h = idx / NP, p = idx % NP;
            int t = (row_of_p(p) * h) % NH;
            float s, c; sincospif(2.0f * (float)t / (float)NH, &s, &c);
            g_CH[idx] = c; g_SH[idx] = s;
        }
        {
            int p = idx / NH, h = idx % NH;
            int t = (row_of_p(p) * h) % NH;
            float s, c; sincospif(2.0f * (float)t / (float)NH, &s, &c);
            g_CI[idx] = c * (1.0f / (float)NH);
            g_SI[idx] = s * (1.0f / (float)NH);
        }
    }
    // g_DI[jc][w]: out[w] = Re(T0)/W + sum_{j>=1} (2/W)(Re Tj cos - Im Tj sin)
    if (idx < NJC * NW) {
        int jc = idx / NW, w = idx % NW, j = jc >> 1;
        int t = (j * w) % NW;
        float s, c; sincospif(2.0f * (float)t / (float)NW, &s, &c);
        float v;
        if (j == 0) v = (jc & 1) ? 0.0f : (1.0f / (float)NW);
        else        v = (jc & 1) ? (-2.0f / (float)NW) * s : (2.0f / (float)NW) * c;
        g_DI[idx] = v;
    }
}

// ---------------- weight transpose: [c][o][i][j] -> [p][j][c][o][2] ----------------
__global__ void prep_w(const float* __restrict__ w1r, const float* __restrict__ w1i,
                       const float* __restrict__ w2r, const float* __restrict__ w2i) {
    int idx = blockIdx.x * blockDim.x + threadIdx.x;  // over NP*NJ*NC*NC = 2097152
    if (idx >= NP * NJ * NC * NC) return;
    int o = idx % NC;
    int c = (idx / NC) % NC;
    int j = (idx / (NC * NC)) % NJ;
    int p = idx / (NC * NC * NJ);
    int i = (p < 32) ? p : (p - 32);
    const float* wr = (p < 32) ? w1r : w2r;
    const float* wi = (p < 32) ? w1i : w2i;
    int widx = ((c * NC + o) * 32 + i) * 32 + j;
    g_Wmix[(size_t)idx * 2 + 0] = wr[widx];
    g_Wmix[(size_t)idx * 2 + 1] = wi[widx];
}

// ---------------- generic fp32 GEMM: C[M,N] = A[M,K]*B[K,N], BM=128 BN=64 BK=16 ----------------
__global__ __launch_bounds__(256) void gemm_k(const float* __restrict__ A,
                                              const float* __restrict__ B,
                                              float* __restrict__ Cm,
                                              int K, int N) {
    __shared__ float As[16][128];
    __shared__ float Bs[16][64];
    int m0 = blockIdx.y * 128;
    int n0 = blockIdx.x * 64;
    int t  = threadIdx.x;
    int tx = t & 15, ty = t >> 4;

    float acc[8][4];
#pragma unroll
    for (int i = 0; i < 8; i++)
#pragma unroll
        for (int j = 0; j < 4; j++) acc[i][j] = 0.0f;

    for (int k0 = 0; k0 < K; k0 += 16) {
        // load A tile: 128 rows x 16 k
        {
            int row = t >> 1;
            int kf  = (t & 1) * 8;
            const float* ap = A + (size_t)(m0 + row) * K + k0 + kf;
            float4 v0 = *(const float4*)ap;
            float4 v1 = *(const float4*)(ap + 4);
            As[kf + 0][row] = v0.x; As[kf + 1][row] = v0.y;
            As[kf + 2][row] = v0.z; As[kf + 3][row] = v0.w;
            As[kf + 4][row] = v1.x; As[kf + 5][row] = v1.y;
            As[kf + 6][row] = v1.z; As[kf + 7][row] = v1.w;
        }
        // load B tile: 16 rows x 64 n
        {
            int kk = t >> 4;
            int nf = (t & 15) * 4;
            *(float4*)&Bs[kk][nf] = *(const float4*)(B + (size_t)(k0 + kk) * N + n0 + nf);
        }
        __syncthreads();
#pragma unroll
        for (int kk = 0; kk < 16; kk++) {
            float4 a0 = *(float4*)&As[kk][ty * 8];
            float4 a1 = *(float4*)&As[kk][ty * 8 + 4];
            float4 bv = *(float4*)&Bs[kk][tx * 4];
            float a[8] = {a0.x, a0.y, a0.z, a0.w, a1.x, a1.y, a1.z, a1.w};
            float b[4] = {bv.x, bv.y, bv.z, bv.w};
#pragma unroll
            for (int i = 0; i < 8; i++)
#pragma unroll
                for (int j = 0; j < 4; j++) acc[i][j] += a[i] * b[j];
        }
        __syncthreads();
    }
#pragma unroll
    for (int i = 0; i < 8; i++) {
        float4 v = make_float4(acc[i][0], acc[i][1], acc[i][2], acc[i][3]);
        *(float4*)&Cm[(size_t)(m0 + ty * 8 + i) * N + n0 + tx * 4] = v;
    }
}

// ---------------- forward H-DFT per (bl,c) batch ----------------
// in: T[batch][h=128][jc=64] interleaved (Tr,Ti). out: Z[batch][p=64][j=32][2]
// Z = sum_h (cos - i sin)(Tr + i Ti): Zr = c*Tr + s*Ti ; Zi = c*Ti - s*Tr
__global__ __launch_bounds__(256) void fwdH(const float* __restrict__ Tin,
                                            float* __restrict__ Zout) {
    int batch = blockIdx.x;
    __shared__ float Ts[NH][NJC];  // 32KB
    const float* src = Tin + (size_t)batch * NH * NJC;
    for (int i = threadIdx.x; i < NH * NJC / 4; i += 256)
        ((float4*)Ts)[i] = ((const float4*)src)[i];
    __syncthreads();

    int p  = threadIdx.x & 63;
    int jg = threadIdx.x >> 6;  // 0..3, owns j in [jg*8, jg*8+8)
    float zr[8], zi[8];
#pragma unroll
    for (int u = 0; u < 8; u++) { zr[u] = 0.0f; zi[u] = 0.0f; }

    for (int h = 0; h < NH; h++) {
        float ch = g_CH[h * NP + p];
        float sh = g_SH[h * NP + p];
#pragma unroll
        for (int u = 0; u < 4; u++) {
            float4 v = *(float4*)&Ts[h][jg * 16 + u * 4];  // (Tr,Ti) for 2 j's
            zr[2*u]     += ch * v.x + sh * v.y;
            zi[2*u]     += ch * v.y - sh * v.x;
            zr[2*u + 1] += ch * v.z + sh * v.w;
            zi[2*u + 1] += ch * v.w - sh * v.z;
        }
    }
    float* dst = Zout + (size_t)batch * NP * NJ * 2;
#pragma unroll
    for (int u = 0; u < 8; u++) {
        float2 o = make_float2(zr[u], zi[u]);
        *(float2*)&dst[(p * NJ + jg * 8 + u) * 2] = o;
    }
}

// ---------------- per-mode channel mix: G[bl,o] = sum_c (Z[bl,c]*Kf[c]) * W[c,o] ----------------
__global__ __launch_bounds__(1024) void mix_modes() {
    int mode = blockIdx.x;  // p*32 + j, 2048 blocks
    __shared__ float2 zk[NC][NBL];
    __shared__ float2 ws[NC][NC];
    int t = threadIdx.x;
    {
        int c1 = t >> 5, lo = t & 31;  // lo = bl for zk, = o for ws
        int blc = lo * NC + c1;
        float2 z  = *(const float2*)&g_Z [((size_t)blc * 2048 + mode) * 2];
        float2 kf = *(const float2*)&g_Kf[((size_t)c1  * 2048 + mode) * 2];
        zk[c1][lo] = make_float2(z.x * kf.x - z.y * kf.y, z.x * kf.y + z.y * kf.x);
        ws[c1][lo] = ((const float2*)(g_Wmix + (size_t)mode * NC * NC * 2))[t];
    }
    __syncthreads();
    int o = t & 31, bl = t >> 5;
    float ar = 0.0f, ai = 0.0f;
#pragma unroll
    for (int c = 0; c < NC; c++) {
        float2 w = ws[c][o];
        float2 x = zk[c][bl];
        ar += w.x * x.x - w.y * x.y;
        ai += w.x * x.y + w.y * x.x;
    }
    *(float2*)&g_G[((size_t)(bl * NC + o) * 2048 + mode) * 2] = make_float2(ar, ai);
}

// ---------------- inverse H (full complex ifft restricted to kept rows) ----------------
// tmp[h,j] = (1/H) sum_p G[p,j] * exp(+2*pi*i*row(p)*h/H)
__global__ __launch_bounds__(256) void invH(void) {
    int blo = blockIdx.x;  // 1024
    __shared__ float Gs[NP][NJC];  // 16KB
    const float* src = g_G + (size_t)blo * NP * NJC;
    for (int i = threadIdx.x; i < NP * NJC / 4; i += 256)
        ((float4*)Gs)[i] = ((const float4*)src)[i];
    __syncthreads();

    int h  = threadIdx.x & 127;
    int jg = threadIdx.x >> 7;  // 0..1, owns j in [jg*16, jg*16+16)
    float tr[16], ti[16];
#pragma unroll
    for (int u = 0; u < 16; u++) { tr[u] = 0.0f; ti[u] = 0.0f; }

    for (int p = 0; p < NP; p++) {
        float ci = g_CI[p * NH + h];
        float si = g_SI[p * NH + h];
#pragma unroll
        for (int u = 0; u < 8; u++) {
            float4 v = *(float4*)&Gs[p][jg * 32 + u * 4];  // (Gr,Gi) for 2 j's
            tr[2*u]     += ci * v.x - si * v.y;
            ti[2*u]     += ci * v.y + si * v.x;
            tr[2*u + 1] += ci * v.z - si * v.w;
            ti[2*u + 1] += ci * v.w + si * v.z;
        }
    }
    float* dst = g_tmp + (size_t)blo * NH * NJC + h * NJC + jg * 32;
#pragma unroll
    for (int u = 0; u < 8; u++) {
        float4 o = make_float4(tr[2*u], ti[2*u], tr[2*u + 1], ti[2*u + 1]);
        *(float4*)&dst[u * 4] = o;
    }
}

// ---------------- host launcher ----------------
extern "C" void kernel_launch(void* const* d_in, const int* in_sizes, int n_in,
                              void* d_out, int out_size) {
    const float* x   = (const float*)d_in[0];
    const float* k   = (const float*)d_in[1];
    const float* w1r = (const float*)d_in[2];
    const float* w1i = (const float*)d_in[3];
    const float* w2r = (const float*)d_in[4];
    const float* w2i = (const float*)d_in[5];
    float* out = (float*)d_out;
    (void)in_sizes; (void)n_in; (void)out_size;

    void *pT, *pTk, *pZ, *pKf, *pTmp, *pDW, *pDI;
    cudaGetSymbolAddress(&pT,   g_T);
    cudaGetSymbolAddress(&pTk,  g_Tk);
    cudaGetSymbolAddress(&pZ,   g_Z);
    cudaGetSymbolAddress(&pKf,  g_Kf);
    cudaGetSymbolAddress(&pTmp, g_tmp);
    cudaGetSymbolAddress(&pDW,  g_DW);
    cudaGetSymbolAddress(&pDI,  g_DI);

    init_twiddles<<<64, 256>>>();
    prep_w<<<8192, 256>>>(w1r, w1i, w2r, w2i);

    // forward W-DFT: x rows = (bl,c,h) = 131072, k rows = (c,h) = 4096
    gemm_k<<<dim3(1, 131072 / 128), 256>>>(x, (const float*)pDW, (float*)pT, NW, NJC);
    gemm_k<<<dim3(1, 4096 / 128),   256>>>(k, (const float*)pDW, (float*)pTk, NW, NJC);

    // forward H-DFT
    fwdH<<<NC, 256>>>((const float*)pTk, (float*)pKf);       // k_f
    fwdH<<<NBL * NC, 256>>>((const float*)pT, (float*)pZ);   // x_f

    // per-mode: conv (x_f * k_f) + channel mixing
    mix_modes<<<NP * NJ, 1024>>>();

    // inverse H
    invH<<<NBL * NC, 256>>>();

    // inverse W (c2r) straight into output
    gemm_k<<<dim3(NW / 64, 131072 / 128), 256>>>((const float*)pTmp, (const float*)pDI, out, NJC, NW);
}